// round 1
// baseline (speedup 1.0000x reference)
#include <cuda_runtime.h>
#include <cstdint>

#define NNODES 16384
#define IN_F 128
#define PSI_F 16
#define H1 15
#define H2 25
#define OUT_F 128

#define JCHUNKS 16
#define JSZ 1024            // adjacency rows per j-chunk
#define AGG_THREADS 256
#define COLS_PER_THREAD 4   // -> 1024 columns per block, 16 column blocks

// scratch (no allocation allowed -> __device__ globals)
__device__ float g_h[NNODES * PSI_F];                          // 1 MB
__device__ float g_part[(size_t)JCHUNKS * 17 * NNODES];        // 17.8 MB: [jc][k(0..15)=feat,16=count][i]

// ---------------------------------------------------------------------------
// Kernel A: h = relu(relu(x @ W1 + b1) @ W2 + b2), per node. 128 nodes/block.
// ---------------------------------------------------------------------------
__global__ void __launch_bounds__(128) psi_kernel(
    const float* __restrict__ nodes,
    const float* __restrict__ w1, const float* __restrict__ b1,
    const float* __restrict__ w2, const float* __restrict__ b2)
{
    __shared__ float w1s[IN_F * H1];
    __shared__ float w2s[H1 * PSI_F];
    __shared__ float b1s[H1];
    __shared__ float b2s[PSI_F];
    __shared__ __align__(16) float xs[128][33];   // padded: conflict-free per-node reads

    const int tid = threadIdx.x;
    const int node0 = blockIdx.x * 128;

    for (int i = tid; i < IN_F * H1; i += 128) w1s[i] = w1[i];
    for (int i = tid; i < H1 * PSI_F; i += 128) w2s[i] = w2[i];
    if (tid < H1) b1s[tid] = b1[tid];
    if (tid < PSI_F) b2s[tid] = b2[tid];

    float t[H1];
#pragma unroll
    for (int r = 0; r < H1; r++) t[r] = 0.f;

    for (int cf = 0; cf < 4; cf++) {
        __syncthreads();
        for (int idx = tid; idx < 128 * 32; idx += 128) {
            int nl = idx >> 5, f = idx & 31;
            xs[nl][f] = nodes[(node0 + nl) * IN_F + cf * 32 + f];
        }
        __syncthreads();
#pragma unroll 4
        for (int f = 0; f < 32; f++) {
            float xv = xs[tid][f];
            const float* wr = &w1s[(cf * 32 + f) * H1];
#pragma unroll
            for (int r = 0; r < H1; r++) t[r] = fmaf(xv, wr[r], t[r]);
        }
    }
#pragma unroll
    for (int r = 0; r < H1; r++) t[r] = fmaxf(t[r] + b1s[r], 0.f);

    float hv[PSI_F];
#pragma unroll
    for (int k = 0; k < PSI_F; k++) hv[k] = b2s[k];
#pragma unroll
    for (int r = 0; r < H1; r++) {
#pragma unroll
        for (int k = 0; k < PSI_F; k++) hv[k] = fmaf(t[r], w2s[r * PSI_F + k], hv[k]);
    }

    float4* hout = reinterpret_cast<float4*>(&g_h[(size_t)(node0 + tid) * PSI_F]);
#pragma unroll
    for (int q = 0; q < 4; q++) {
        float4 v;
        v.x = fmaxf(hv[q * 4 + 0], 0.f);
        v.y = fmaxf(hv[q * 4 + 1], 0.f);
        v.z = fmaxf(hv[q * 4 + 2], 0.f);
        v.w = fmaxf(hv[q * 4 + 3], 0.f);
        hout[q] = v;
    }
}

// ---------------------------------------------------------------------------
// Kernel B: aggregation. partial[jc][k][i] = sum_{j in chunk jc} A[j,i]*h[j,k]
//           partial[jc][16][i] = count. Packed f32x2 FMAs, alu-pipe 0/1->float.
// ---------------------------------------------------------------------------
__device__ __forceinline__ void ffma2(unsigned long long& d,
                                      unsigned long long a,
                                      unsigned long long b)
{
    asm("fma.rn.f32x2 %0, %1, %2, %0;" : "+l"(d) : "l"(a), "l"(b));
}

__global__ void __launch_bounds__(AGG_THREADS, 2) agg_kernel(const int* __restrict__ A)
{
    const int tid = threadIdx.x;
    const int icol0 = blockIdx.x * (AGG_THREADS * COLS_PER_THREAD) + tid * COLS_PER_THREAD;
    const int j0 = blockIdx.y * JSZ;

    __shared__ __align__(16) float hs[256][PSI_F];   // 16 KB

    unsigned long long acc[COLS_PER_THREAD * 8];     // 4 cols x 8 f32x2 pairs = 64 floats
#pragma unroll
    for (int p = 0; p < COLS_PER_THREAD * 8; p++) acc[p] = 0ull;
    int cnt[COLS_PER_THREAD] = {0, 0, 0, 0};

    for (int js = 0; js < JSZ; js += 256) {
        __syncthreads();
        {
            const float4* src = reinterpret_cast<const float4*>(&g_h[(size_t)(j0 + js) * PSI_F]);
            float4* dst = reinterpret_cast<float4*>(&hs[0][0]);
            for (int idx = tid; idx < 256 * PSI_F / 4; idx += AGG_THREADS) dst[idx] = src[idx];
        }
        __syncthreads();

        const int* Ap = A + (size_t)(j0 + js) * NNODES + icol0;
#pragma unroll 4
        for (int jj = 0; jj < 256; jj++) {
            int4 a4 = *reinterpret_cast<const int4*>(Ap);
            Ap += NNODES;

            const unsigned long long* hp =
                reinterpret_cast<const unsigned long long*>(&hs[jj][0]);
            unsigned long long h2[8];
#pragma unroll
            for (int p = 0; p < 8; p++) h2[p] = hp[p];

            // col 0
            {
                unsigned int b = (unsigned int)(-a4.x) & 0x3F800000u;  // alu pipe: IADD3+LOP3
                unsigned long long f2 = ((unsigned long long)b << 32) | b;
                cnt[0] += a4.x;
#pragma unroll
                for (int p = 0; p < 8; p++) ffma2(acc[0 * 8 + p], h2[p], f2);
            }
            // col 1
            {
                unsigned int b = (unsigned int)(-a4.y) & 0x3F800000u;
                unsigned long long f2 = ((unsigned long long)b << 32) | b;
                cnt[1] += a4.y;
#pragma unroll
                for (int p = 0; p < 8; p++) ffma2(acc[1 * 8 + p], h2[p], f2);
            }
            // col 2
            {
                unsigned int b = (unsigned int)(-a4.z) & 0x3F800000u;
                unsigned long long f2 = ((unsigned long long)b << 32) | b;
                cnt[2] += a4.z;
#pragma unroll
                for (int p = 0; p < 8; p++) ffma2(acc[2 * 8 + p], h2[p], f2);
            }
            // col 3
            {
                unsigned int b = (unsigned int)(-a4.w) & 0x3F800000u;
                unsigned long long f2 = ((unsigned long long)b << 32) | b;
                cnt[3] += a4.w;
#pragma unroll
                for (int p = 0; p < 8; p++) ffma2(acc[3 * 8 + p], h2[p], f2);
            }
        }
    }

    // write partials: coalesced per k across the warp
    const size_t base = (size_t)blockIdx.y * 17 * NNODES + icol0;
#pragma unroll
    for (int c = 0; c < COLS_PER_THREAD; c++) {
#pragma unroll
        for (int p = 0; p < 8; p++) {
            unsigned long long v = acc[c * 8 + p];
            g_part[base + (size_t)(2 * p) * NNODES + c] =
                __uint_as_float((unsigned int)(v & 0xFFFFFFFFull));
            g_part[base + (size_t)(2 * p + 1) * NNODES + c] =
                __uint_as_float((unsigned int)(v >> 32));
        }
        g_part[base + (size_t)16 * NNODES + c] = (float)cnt[c];
    }
}

// ---------------------------------------------------------------------------
// Kernel C: reduce partials -> psi_out; out = relu(relu([x|psi]@fiW1+b1)@fiW2+b2)
// 128 nodes per block, thread = node for phase 1; thread = output-channel phase 2.
// ---------------------------------------------------------------------------
__global__ void __launch_bounds__(128) fin_kernel(
    const float* __restrict__ nodes,
    const float* __restrict__ w1, const float* __restrict__ b1,
    const float* __restrict__ w2, const float* __restrict__ b2,
    float* __restrict__ out)
{
    __shared__ float ws[(IN_F + PSI_F) * H2];        // 144*25 = 14.4 KB
    __shared__ float b1s[H2];
    __shared__ __align__(16) float xs[128][33];      // 16.9 KB
    __shared__ float gs[128][H2];                    // 12.8 KB

    const int tid = threadIdx.x;
    const int node0 = blockIdx.x * 128;
    const int node = node0 + tid;

    for (int i = tid; i < (IN_F + PSI_F) * H2; i += 128) ws[i] = w1[i];
    if (tid < H2) b1s[tid] = b1[tid];

    float g[H2];
#pragma unroll
    for (int r = 0; r < H2; r++) g[r] = 0.f;

    for (int cf = 0; cf < 4; cf++) {
        __syncthreads();
        for (int idx = tid; idx < 128 * 32; idx += 128) {
            int nl = idx >> 5, f = idx & 31;
            xs[nl][f] = nodes[(node0 + nl) * IN_F + cf * 32 + f];
        }
        __syncthreads();
#pragma unroll 4
        for (int f = 0; f < 32; f++) {
            float xv = xs[tid][f];
            const float* wr = &ws[(cf * 32 + f) * H2];
#pragma unroll
            for (int r = 0; r < H2; r++) g[r] = fmaf(xv, wr[r], g[r]);
        }
    }

    // reduce partials for this node
    float cntv = 0.f;
#pragma unroll
    for (int jc = 0; jc < JCHUNKS; jc++)
        cntv += g_part[((size_t)jc * 17 + 16) * NNODES + node];
    float inv = 1.f / cntv;

#pragma unroll
    for (int k = 0; k < PSI_F; k++) {
        float s = 0.f;
#pragma unroll
        for (int jc = 0; jc < JCHUNKS; jc++)
            s += g_part[((size_t)jc * 17 + k) * NNODES + node];
        s *= inv;
        const float* wr = &ws[(IN_F + k) * H2];
#pragma unroll
        for (int r = 0; r < H2; r++) g[r] = fmaf(s, wr[r], g[r]);
    }

#pragma unroll
    for (int r = 0; r < H2; r++) gs[tid][r] = fmaxf(g[r] + b1s[r], 0.f);
    __syncthreads();

    // phase 2: thread tid owns output channel tid for all 128 nodes (coalesced STG)
    float w2r[H2];
#pragma unroll
    for (int r = 0; r < H2; r++) w2r[r] = w2[r * OUT_F + tid];
    float b2v = b2[tid];

    for (int n = 0; n < 128; n++) {
        float o = b2v;
#pragma unroll
        for (int r = 0; r < H2; r++) o = fmaf(gs[n][r], w2r[r], o);
        out[(size_t)(node0 + n) * OUT_F + tid] = fmaxf(o, 0.f);
    }
}

// ---------------------------------------------------------------------------
extern "C" void kernel_launch(void* const* d_in, const int* in_sizes, int n_in,
                              void* d_out, int out_size)
{
    const float* nodes  = (const float*)d_in[0];
    const int*   adj    = (const int*)  d_in[1];
    const float* psi_w1 = (const float*)d_in[2];
    const float* psi_b1 = (const float*)d_in[3];
    const float* psi_w2 = (const float*)d_in[4];
    const float* psi_b2 = (const float*)d_in[5];
    const float* fi_w1  = (const float*)d_in[6];
    const float* fi_b1  = (const float*)d_in[7];
    const float* fi_w2  = (const float*)d_in[8];
    const float* fi_b2  = (const float*)d_in[9];
    float* out = (float*)d_out;

    psi_kernel<<<NNODES / 128, 128>>>(nodes, psi_w1, psi_b1, psi_w2, psi_b2);
    agg_kernel<<<dim3(NNODES / (AGG_THREADS * COLS_PER_THREAD), JCHUNKS), AGG_THREADS>>>(adj);
    fin_kernel<<<NNODES / 128, 128>>>(nodes, fi_w1, fi_b1, fi_w2, fi_b2, out);
}